// round 2
// baseline (speedup 1.0000x reference)
#include <cuda_runtime.h>
#include <cuda_bf16.h>

#define LRELU_ALPHA 0.2f
#define MASK_VAL -9000000000000000.0f

using ull = unsigned long long;

// packed dual-fp32 FMA (sm_100+): d = a*b + d on two f32 lanes
__device__ __forceinline__ void ffma2(ull& d, ull a, ull b) {
    asm("fma.rn.f32x2 %0, %1, %2, %0;" : "+l"(d) : "l"(a), "l"(b));
}
__device__ __forceinline__ float2 unpack2(ull v) {
    float2 r; asm("mov.b64 {%0, %1}, %2;" : "=f"(r.x), "=f"(r.y) : "l"(v));
    return r;
}

// ---- shared-memory layout (units: floats) ----
#define OFF_W2P 0            // W2 pair-packed: 96*32 float2 = 6144 floats
#define OFF_VP  6144         // v1/v2 pairs: 3*98 float2 = 588 floats
#define OFF_WP1 6732         // Wp1 dup pairs: 48*32 float2 = 3072 floats
#define OFF_W1F 9804         // W1 flat: 96
#define OFF_C   9900         // c1[3], c2[3] (+2 pad)
#define CONSTF  9908
#define H1F2    1764         // h1 dup pairs: 9 rows * 98 float2 (overlaid by h2T later)
#define WSTR    2180         // per-warp floats: 1764 + 324(att) + 64(f) + 28(s1)
#define NWARPS  8
#define SMEMF   (CONSTF + NWARPS*WSTR)
#define SMEMB   (SMEMF * 4)

__global__ void __launch_bounds__(256, 2)
gnn_kernel(const float* __restrict__ g_obs, const float* __restrict__ g_adj,
           const float* __restrict__ g_W1, const float* __restrict__ g_a1,
           const float* __restrict__ g_W2, const float* __restrict__ g_a2,
           const float* __restrict__ g_Wp1, const float* __restrict__ g_bp1,
           const float* __restrict__ g_Wp2, const float* __restrict__ g_bp2,
           float* __restrict__ g_out, int B)
{
    extern __shared__ float sm[];
    const int tid  = threadIdx.x;
    const int lane = tid & 31;
    const int wrp  = tid >> 5;

    // ================= per-block weight preprocessing =================
    // W2full[k][c], c = h*16+d  (W2 is [3][96][16]); cols 48..63 zero-padded.
    // pair (c, c+32) packed as float2 at float2-index k*32 + c.
    for (int idx = tid; idx < 96*32; idx += 256) {
        int k = idx >> 5, l = idx & 31;
        float wA = g_W2[(l >> 4)*1536 + k*16 + (l & 15)];
        float wB = (l < 16) ? g_W2[2*1536 + k*16 + l] : 0.f;
        sm[OFF_W2P + 2*idx]     = wA;
        sm[OFF_W2P + 2*idx + 1] = wB;
    }
    // v1[h][k] = W2[h,k,:16]·a2[h,:16] ; v2[h][k] with a2[h,16:32]
    for (int idx = tid; idx < 3*96; idx += 256) {
        int h = idx / 96, k = idx - h*96;
        float v1 = 0.f, v2 = 0.f;
        #pragma unroll
        for (int d = 0; d < 16; d++) {
            float w = g_W2[h*1536 + k*16 + d];
            v1 += w * g_a2[h*32 + d];
            v2 += w * g_a2[h*32 + 16 + d];
        }
        sm[OFF_VP + 2*(h*98 + k)]     = v1;
        sm[OFF_VP + 2*(h*98 + k) + 1] = v2;
    }
    // Wp1 dup-pairs: float2-index c*32 + l -> {w,w}, zero for l>=24
    for (int idx = tid; idx < 48*32; idx += 256) {
        int c = idx >> 5, l = idx & 31;
        float w = (l < 24) ? g_Wp1[c*24 + l] : 0.f;
        sm[OFF_WP1 + 2*idx]     = w;
        sm[OFF_WP1 + 2*idx + 1] = w;
    }
    for (int idx = tid; idx < 96; idx += 256) sm[OFF_W1F + idx] = g_W1[idx];
    if (tid < 3) {  // c1[h] = W1[h,:]·a1[h,:32]; c2[h] = W1[h,:]·a1[h,32:64]
        float c1 = 0.f, c2 = 0.f;
        #pragma unroll
        for (int d = 0; d < 32; d++) {
            float w = g_W1[tid*32 + d];
            c1 += w * g_a1[tid*64 + d];
            c2 += w * g_a1[tid*64 + 32 + d];
        }
        sm[OFF_C + tid]     = c1;
        sm[OFF_C + 3 + tid] = c2;
    }
    __syncthreads();

    // ================= per-warp pointers & loop-invariant registers =================
    float* swp = sm + CONSTF + wrp * WSTR;
    float2* Hd  = (float2*)swp;           // h1 dup pairs [9][98]
    ull*    Hu  = (ull*)swp;
    float*  h2f = swp;                    // overlays Hd after GEMM: h2T[48][10]
    const ull* h2u = (const ull*)swp;
    float* atts = swp + H1F2;             // att2 [27][12]
    float* fs   = swp + H1F2 + 324;       // f1[27] @0, f2[27] @32
    float* s1s  = swp + H1F2 + 324 + 64;  // s1 [27]
    const ull* W2PU = (const ull*)(sm + OFF_W2P);
    const ull* VPU  = (const ull*)(sm + OFF_VP);
    const ull* WP1U = (const ull*)(sm + OFF_WP1);

    const float w1r0 = sm[OFF_W1F + lane];
    const float w1r1 = sm[OFF_W1F + lane + 32];
    const float w1r2 = sm[OFF_W1F + lane + 64];
    const float bp1m = (lane < 24) ? g_bp1[lane] : 0.f;
    const float wp2m = (lane < 24) ? g_Wp2[lane] : 0.f;
    const float bp2v = g_bp2[0];

    int hq = 0, iq = 0;
    unsigned mrow = 0x1ffu;
    if (lane < 27) {
        hq = lane / 9; iq = lane - hq*9;
        mrow = 0u;
        #pragma unroll
        for (int j = 0; j < 9; j++)
            if (g_adj[iq*9 + j] > 0.f) mrow |= (1u << j);
    }
    const float c1h = sm[OFF_C + hq];
    const float c2h = sm[OFF_C + 3 + hq];
    const int hA = lane >> 4;             // head owning column 'lane'

    const int nwarp = (gridDim.x * blockDim.x) >> 5;
    const int gw = (blockIdx.x * blockDim.x + tid) >> 5;

    for (int b = gw; b < B; b += nwarp) {
        float o[9];
        #pragma unroll
        for (int n = 0; n < 9; n++) o[n] = g_obs[b*9 + n];

        // ---- layer-1 attention (rank-1): s1[h][i] = att1 @ obs ----
        if (lane < 27) {
            float base = c1h * o[iq];
            float e[9]; float mx = -3.0e38f;
            #pragma unroll
            for (int j = 0; j < 9; j++) {
                float x = base + c2h * o[j];
                x = fmaxf(x, LRELU_ALPHA * x);            // leaky_relu
                if (!((mrow >> j) & 1u)) x = MASK_VAL;
                e[j] = x; mx = fmaxf(mx, x);
            }
            float den = 0.f, num = 0.f;
            #pragma unroll
            for (int j = 0; j < 9; j++) {
                float p = __expf(e[j] - mx);
                den += p; num += p * o[j];
            }
            s1s[lane] = __fdividef(num, den);
        }
        __syncwarp();

        // ---- h1[n][k] = elu(s1[k/32][n] * W1[k]) stored as {v,v} pairs ----
        #pragma unroll
        for (int n = 0; n < 9; n++) {
            float v0 = s1s[0*9 + n] * w1r0;
            float v1 = s1s[1*9 + n] * w1r1;
            float v2 = s1s[2*9 + n] * w1r2;
            v0 = (v0 > 0.f) ? v0 : (__expf(v0) - 1.f);
            v1 = (v1 > 0.f) ? v1 : (__expf(v1) - 1.f);
            v2 = (v2 > 0.f) ? v2 : (__expf(v2) - 1.f);
            Hd[n*98 + lane     ] = make_float2(v0, v0);
            Hd[n*98 + lane + 32] = make_float2(v1, v1);
            Hd[n*98 + lane + 64] = make_float2(v2, v2);
        }
        __syncwarp();

        // ---- layer-2 logits: f1/f2 dual-dot via FFMA2 ----
        if (lane < 27) {
            ull accA = 0ull, accB = 0ull;
            #pragma unroll 8
            for (int k = 0; k < 96; k += 2) {
                ffma2(accA, Hu[iq*98 + k],     VPU[hq*98 + k]);
                ffma2(accB, Hu[iq*98 + k + 1], VPU[hq*98 + k + 1]);
            }
            float2 fa = unpack2(accA), fb = unpack2(accB);
            fs[lane]      = fa.x + fb.x;   // f1[h*9+i]
            fs[32 + lane] = fa.y + fb.y;   // f2[h*9+i]
        }
        __syncwarp();

        // ---- layer-2 attention weights ----
        if (lane < 27) {
            float f1v = fs[lane];
            float e[9]; float mx = -3.0e38f;
            #pragma unroll
            for (int j = 0; j < 9; j++) {
                float x = f1v + fs[32 + hq*9 + j];
                x = fmaxf(x, LRELU_ALPHA * x);
                if (!((mrow >> j) & 1u)) x = MASK_VAL;
                e[j] = x; mx = fmaxf(mx, x);
            }
            float den = 0.f;
            #pragma unroll
            for (int j = 0; j < 9; j++) { e[j] = __expf(e[j] - mx); den += e[j]; }
            float inv = __fdividef(1.f, den);
            #pragma unroll
            for (int j = 0; j < 9; j++) atts[lane*12 + j] = e[j] * inv;
        }
        __syncwarp();

        // ---- main GEMM: Wh2[9][48] = h1[9][96] @ W2full[96][48] via FFMA2 ----
        // lane owns column pair (lane, lane+32); pad cols 48..63 are zero.
        ull acc[9];
        #pragma unroll
        for (int n = 0; n < 9; n++) acc[n] = 0ull;
        #pragma unroll 2
        for (int kc = 0; kc < 96; kc += 4) {
            ull w0 = W2PU[(kc+0)*32 + lane];
            ull w1 = W2PU[(kc+1)*32 + lane];
            ull w2 = W2PU[(kc+2)*32 + lane];
            ull w3 = W2PU[(kc+3)*32 + lane];
            #pragma unroll
            for (int n = 0; n < 9; n++) {
                const ulonglong2* hp = (const ulonglong2*)(Hu + n*98 + kc);
                ulonglong2 ha = hp[0];
                ulonglong2 hb = hp[1];
                ffma2(acc[n], ha.x, w0);
                ffma2(acc[n], ha.y, w1);
                ffma2(acc[n], hb.x, w2);
                ffma2(acc[n], hb.y, w3);
            }
        }

        // ---- apply attention: h2[i][c] = sum_j att2[head(c)][i][j] * Wh2[j][c] ----
        float aLo[9], aHi[9];
        #pragma unroll
        for (int n = 0; n < 9; n++) { float2 t = unpack2(acc[n]); aLo[n] = t.x; aHi[n] = t.y; }
        const float* attA = atts + hA*108;   // head of col 'lane'
        const float* attB = atts + 216;      // head 2 (cols 32..47)
        float h2a[9], h2b[9];
        #pragma unroll
        for (int i = 0; i < 9; i++) {
            float sa = 0.f, sb = 0.f;
            #pragma unroll
            for (int j = 0; j < 9; j++) {
                sa += attA[i*12 + j] * aLo[j];
                sb += attB[i*12 + j] * aHi[j];
            }
            h2a[i] = sa; h2b[i] = sb;
        }
        __syncwarp();   // all lanes done reading Hu before overwriting with h2T

        // ---- stage h2 transposed: h2T[c][10] (elem 9 zero-padded) ----
        #pragma unroll
        for (int i = 0; i < 9; i++) h2f[lane*10 + i] = h2a[i];
        h2f[lane*10 + 9] = 0.f;
        if (lane < 16) {
            #pragma unroll
            for (int i = 0; i < 9; i++) h2f[(lane+32)*10 + i] = h2b[i];
            h2f[(lane+32)*10 + 9] = 0.f;
        }
        __syncwarp();

        // ---- pooling GEMM: U[n][lane] = sum_c h2[n][c]*Wp1[c][lane], FFMA2 row pairs ----
        ull up0=0ull, up1=0ull, up2=0ull, up3=0ull, up4=0ull;
        #pragma unroll 4
        for (int c = 0; c < 48; c++) {
            ull w = WP1U[c*32 + lane];
            ffma2(up0, h2u[c*5 + 0], w);
            ffma2(up1, h2u[c*5 + 1], w);
            ffma2(up2, h2u[c*5 + 2], w);
            ffma2(up3, h2u[c*5 + 3], w);
            ffma2(up4, h2u[c*5 + 4], w);
        }
        float U[9];
        { float2 t;
          t = unpack2(up0); U[0]=t.x; U[1]=t.y;
          t = unpack2(up1); U[2]=t.x; U[3]=t.y;
          t = unpack2(up2); U[4]=t.x; U[5]=t.y;
          t = unpack2(up3); U[6]=t.x; U[7]=t.y;
          t = unpack2(up4); U[8]=t.x; }

        // scores[n]: lanes>=24 contribute 0 (wp2m=0); warp-reduce over m
        float sc[9];
        #pragma unroll
        for (int n = 0; n < 9; n++) {
            float t = tanhf(U[n] + bp1m) * wp2m;
            #pragma unroll
            for (int off = 16; off > 0; off >>= 1)
                t += __shfl_xor_sync(0xffffffffu, t, off);
            sc[n] = t + bp2v;
        }
        // softmax over nodes + weighted sum (h2 rows still in registers)
        float mx = sc[0];
        #pragma unroll
        for (int n = 1; n < 9; n++) mx = fmaxf(mx, sc[n]);
        float den = 0.f;
        #pragma unroll
        for (int n = 0; n < 9; n++) { sc[n] = __expf(sc[n] - mx); den += sc[n]; }
        float inv = __fdividef(1.f, den);
        float ra = 0.f, rb = 0.f;
        #pragma unroll
        for (int n = 0; n < 9; n++) {
            float wn = sc[n] * inv;
            ra += wn * h2a[n];
            rb += wn * h2b[n];
        }
        g_out[b*48 + lane] = ra;
        if (lane < 16) g_out[b*48 + 32 + lane] = rb;
        __syncwarp();   // protect h2f before next iteration's Hd writes
    }
}

extern "C" void kernel_launch(void* const* d_in, const int* in_sizes, int n_in,
                              void* d_out, int out_size) {
    const float* obs = (const float*)d_in[0];
    const float* adj = (const float*)d_in[1];
    const float* W1  = (const float*)d_in[2];
    const float* a1  = (const float*)d_in[3];
    const float* W2  = (const float*)d_in[4];
    const float* a2  = (const float*)d_in[5];
    const float* Wp1 = (const float*)d_in[6];
    const float* bp1 = (const float*)d_in[7];
    const float* Wp2 = (const float*)d_in[8];
    const float* bp2 = (const float*)d_in[9];
    float* out = (float*)d_out;
    int B = in_sizes[0] / 9;

    cudaFuncSetAttribute(gnn_kernel,
                         cudaFuncAttributeMaxDynamicSharedMemorySize, SMEMB);

    int blocks = 304;  // 2 per SM on 152-SM GB300 (persistent grid-stride)
    gnn_kernel<<<blocks, 256, SMEMB>>>(obs, adj, W1, a1, W2, a2,
                                       Wp1, bp1, Wp2, bp2, out, B);
}

// round 3
// speedup vs baseline: 1.0959x; 1.0959x over previous
#include <cuda_runtime.h>
#include <cuda_bf16.h>

#define ALPHA 0.2f
#define MASKV -9000000000000000.0f

using ull = unsigned long long;

// ---------------- constant-bank weights (copied DtoD each launch) -------------
__constant__ float cW1[96];     // (3,1,32)
__constant__ float cA1[192];    // (3,64,1)
__constant__ float cW2[4608];   // (3,96,16)
__constant__ float cA2[96];     // (3,32,1)
__constant__ float cWp1[1152];  // (48,24)
__constant__ float cBp1[24];
__constant__ float cWp2[24];
__constant__ float cBp2[1];
__constant__ float cAdj[81];

#define NBLK 304
#define NTHR 128
#define NTOT (NBLK*NTHR)
// per-thread h2 [9][48], lane-interleaved for coalescing
__device__ float g_h2[NTOT * 432];

__device__ __forceinline__ void ffma2(ull& d, ull a, ull b) {
    asm("fma.rn.f32x2 %0, %1, %2, %0;" : "+l"(d) : "l"(a), "l"(b));
}
__device__ __forceinline__ ull dup2(float x) {
    ull r; asm("mov.b64 %0, {%1, %1};" : "=l"(r) : "f"(x)); return r;
}
__device__ __forceinline__ ull pack2(float x, float y) {
    ull r; asm("mov.b64 %0, {%1, %2};" : "=l"(r) : "f"(x), "f"(y)); return r;
}
__device__ __forceinline__ float2 unp(ull v) {
    float2 r; asm("mov.b64 {%0, %1}, %2;" : "=f"(r.x), "=f"(r.y) : "l"(v)); return r;
}
__device__ __forceinline__ float tanh_fast(float x) {
    float r; asm("tanh.approx.f32 %0, %1;" : "=f"(r) : "f"(x)); return r;
}
// 8-byte load from constant bank (8B-aligned offsets only)
__device__ __forceinline__ ull c64(const float* p) {
    return __double_as_longlong(*(const double*)(const void*)p);
}
__device__ __forceinline__ float lrelu(float x) { return fmaxf(x, ALPHA * x); }

__global__ void __launch_bounds__(NTHR, 2)
gnn_tpg(const float* __restrict__ g_obs, float* __restrict__ g_out, int B)
{
    const int gtid = blockIdx.x * NTHR + threadIdx.x;
    const int nthr = gridDim.x * NTHR;
    float* h2base = g_h2 + gtid;   // element i at h2base[i*nthr]

    // ---- loop-invariant: c1/c2 and adjacency masks ----
    float c1[3], c2[3];
    #pragma unroll
    for (int h = 0; h < 3; h++) {
        float a = 0.f, b = 0.f;
        #pragma unroll
        for (int d = 0; d < 32; d++) {
            float w = cW1[h*32 + d];
            a += w * cA1[h*64 + d];
            b += w * cA1[h*64 + 32 + d];
        }
        c1[h] = a; c2[h] = b;
    }
    unsigned mrow[9];
    #pragma unroll
    for (int i = 0; i < 9; i++) {
        unsigned m = 0;
        #pragma unroll
        for (int j = 0; j < 9; j++)
            if (cAdj[i*9 + j] > 0.f) m |= (1u << j);
        mrow[i] = m;
    }

    for (int b = gtid; b < B; b += nthr) {
        float o[9];
        #pragma unroll
        for (int n = 0; n < 9; n++) o[n] = g_obs[b*9 + n];

        // ---- layer-1 attention (rank-1 collapse): s1[h][n] = att1 @ obs ----
        float s1[3][9];
        #pragma unroll
        for (int h = 0; h < 3; h++) {
            float g[9];
            #pragma unroll
            for (int j = 0; j < 9; j++) g[j] = c2[h] * o[j];
            #pragma unroll
            for (int i = 0; i < 9; i++) {
                float fi = c1[h] * o[i];
                float e[9], mx = -3.0e38f;
                #pragma unroll
                for (int j = 0; j < 9; j++) {
                    float x = lrelu(fi + g[j]);
                    if (!((mrow[i] >> j) & 1u)) x = MASKV;
                    e[j] = x; mx = fmaxf(mx, x);
                }
                float den = 0.f, num = 0.f;
                #pragma unroll
                for (int j = 0; j < 9; j++) {
                    float p = __expf(e[j] - mx);
                    den += p; num += p * o[j];
                }
                s1[h][i] = __fdividef(num, den);
            }
        }

        // ---- layer 2, one head (16 output cols) at a time ----
        #pragma unroll
        for (int H = 0; H < 3; H++) {
            // Wh2[n][H*16 + 2cp..2cp+1] accumulated as f32x2 pairs
            ull acc[9][8];
            #pragma unroll
            for (int n = 0; n < 9; n++)
                #pragma unroll
                for (int cp = 0; cp < 8; cp++) acc[n][cp] = 0ull;

            #pragma unroll
            for (int kh = 0; kh < 3; kh++) {
                #pragma unroll 2
                for (int d = 0; d < 32; d++) {
                    int k = kh*32 + d;
                    float w1 = cW1[k];
                    // h1[n][k] = elu(s1[kh][n] * W1[k]) recomputed on the fly
                    ull hp[9];
                    #pragma unroll
                    for (int n = 0; n < 9; n++) {
                        float x = s1[kh][n] * w1;
                        x = (x > 0.f) ? x : (__expf(x) - 1.f);
                        hp[n] = dup2(x);
                    }
                    const float* wrow = &cW2[H*1536 + k*16];
                    #pragma unroll
                    for (int cp = 0; cp < 8; cp++) {
                        ull wp = c64(wrow + 2*cp);          // {W2[k][2cp], W2[k][2cp+1]}
                        #pragma unroll
                        for (int n = 0; n < 9; n++) ffma2(acc[n][cp], hp[n], wp);
                    }
                }
            }

            // f1/f2 from accumulated Wh tile (a2 halves)
            float f1[9], f2[9];
            #pragma unroll
            for (int i = 0; i < 9; i++) {
                float a = 0.f, b2 = 0.f;
                #pragma unroll
                for (int cp = 0; cp < 8; cp++) {
                    float2 t = unp(acc[i][cp]);
                    a  += t.x * cA2[H*32 + 2*cp]      + t.y * cA2[H*32 + 2*cp + 1];
                    b2 += t.x * cA2[H*32 + 16 + 2*cp] + t.y * cA2[H*32 + 17 + 2*cp];
                }
                f1[i] = a; f2[i] = b2;
            }

            // row max + inverse denominator
            float mxr[9], inv[9];
            #pragma unroll
            for (int i = 0; i < 9; i++) {
                float e[9], mx = -3.0e38f;
                #pragma unroll
                for (int j = 0; j < 9; j++) {
                    float x = lrelu(f1[i] + f2[j]);
                    if (!((mrow[i] >> j) & 1u)) x = MASKV;
                    e[j] = x; mx = fmaxf(mx, x);
                }
                float den = 0.f;
                #pragma unroll
                for (int j = 0; j < 9; j++) den += __expf(e[j] - mx);
                mxr[i] = mx; inv[i] = __fdividef(1.f, den);
            }

            // apply attention row by row; write h2 rows straight to scratch
            #pragma unroll
            for (int i = 0; i < 9; i++) {
                ull r[8];
                #pragma unroll
                for (int cp = 0; cp < 8; cp++) r[cp] = 0ull;
                #pragma unroll
                for (int j = 0; j < 9; j++) {
                    float x = lrelu(f1[i] + f2[j]);
                    if (!((mrow[i] >> j) & 1u)) x = MASKV;
                    float w = __expf(x - mxr[i]) * inv[i];
                    ull wp = dup2(w);
                    #pragma unroll
                    for (int cp = 0; cp < 8; cp++) ffma2(r[cp], acc[j][cp], wp);
                }
                #pragma unroll
                for (int cp = 0; cp < 8; cp++) {
                    float2 t = unp(r[cp]);
                    h2base[(i*48 + H*16 + 2*cp    ) * nthr] = t.x;
                    h2base[(i*48 + H*16 + 2*cp + 1) * nthr] = t.y;
                }
            }
        }

        // ---- pooling: U[n] = h2[n] @ Wp1 + bp1; score[n] = tanh(U)·Wp2 + bp2 ----
        float score[9];
        #pragma unroll
        for (int n = 0; n < 9; n++) {
            ull U[12];
            #pragma unroll
            for (int mp = 0; mp < 12; mp++) U[mp] = pack2(cBp1[2*mp], cBp1[2*mp+1]);
            #pragma unroll 8
            for (int c = 0; c < 48; c++) {
                float hv = h2base[(n*48 + c) * nthr];
                ull hp = dup2(hv);
                #pragma unroll
                for (int mp = 0; mp < 12; mp++)
                    ffma2(U[mp], hp, c64(&cWp1[c*24 + 2*mp]));
            }
            float s = cBp2[0];
            #pragma unroll
            for (int mp = 0; mp < 12; mp++) {
                float2 t = unp(U[mp]);
                s += tanh_fast(t.x) * cWp2[2*mp] + tanh_fast(t.y) * cWp2[2*mp+1];
            }
            score[n] = s;
        }

        // softmax over nodes
        float mx = score[0];
        #pragma unroll
        for (int n = 1; n < 9; n++) mx = fmaxf(mx, score[n]);
        float den = 0.f;
        #pragma unroll
        for (int n = 0; n < 9; n++) { score[n] = __expf(score[n] - mx); den += score[n]; }
        float inv = __fdividef(1.f, den);
        #pragma unroll
        for (int n = 0; n < 9; n++) score[n] *= inv;

        // out[c] = sum_n w[n] * h2[n][c], vectorized stores
        #pragma unroll
        for (int c4 = 0; c4 < 12; c4++) {
            float4 r = make_float4(0.f, 0.f, 0.f, 0.f);
            #pragma unroll
            for (int n = 0; n < 9; n++) {
                float wn = score[n];
                int base = n*48 + c4*4;
                r.x += wn * h2base[(base + 0) * nthr];
                r.y += wn * h2base[(base + 1) * nthr];
                r.z += wn * h2base[(base + 2) * nthr];
                r.w += wn * h2base[(base + 3) * nthr];
            }
            *(float4*)&g_out[b*48 + c4*4] = r;
        }
    }
}

extern "C" void kernel_launch(void* const* d_in, const int* in_sizes, int n_in,
                              void* d_out, int out_size) {
    const float* obs = (const float*)d_in[0];
    int B = in_sizes[0] / 9;

    cudaMemcpyToSymbolAsync(cAdj, d_in[1],   81 * 4, 0, cudaMemcpyDeviceToDevice);
    cudaMemcpyToSymbolAsync(cW1,  d_in[2],   96 * 4, 0, cudaMemcpyDeviceToDevice);
    cudaMemcpyToSymbolAsync(cA1,  d_in[3],  192 * 4, 0, cudaMemcpyDeviceToDevice);
    cudaMemcpyToSymbolAsync(cW2,  d_in[4], 4608 * 4, 0, cudaMemcpyDeviceToDevice);
    cudaMemcpyToSymbolAsync(cA2,  d_in[5],   96 * 4, 0, cudaMemcpyDeviceToDevice);
    cudaMemcpyToSymbolAsync(cWp1, d_in[6], 1152 * 4, 0, cudaMemcpyDeviceToDevice);
    cudaMemcpyToSymbolAsync(cBp1, d_in[7],   24 * 4, 0, cudaMemcpyDeviceToDevice);
    cudaMemcpyToSymbolAsync(cWp2, d_in[8],   24 * 4, 0, cudaMemcpyDeviceToDevice);
    cudaMemcpyToSymbolAsync(cBp2, d_in[9],    1 * 4, 0, cudaMemcpyDeviceToDevice);

    gnn_tpg<<<NBLK, NTHR>>>(obs, (float*)d_out, B);
}